// round 1
// baseline (speedup 1.0000x reference)
#include <cuda_runtime.h>
#include <math.h>

#define BB   64
#define LL   900
#define DD   64
#define TILE 64
#define NKT  15      // ceil(900/64) k-tiles (also q-tiles)
#define PAD  65      // smem row pad (floats) -> conflict-light scalar LDS

// Per-row softmax stats scratch (b*L rows). __device__ globals: allowed (no allocs).
__device__ float g_m[BB * LL];
__device__ float g_invl[BB * LL];

__global__ __launch_bounds__(256)
void attn_fused(const float* __restrict__ q, const float* __restrict__ k,
                const float* __restrict__ v, const int* __restrict__ dur,
                float* __restrict__ out, float* __restrict__ score)
{
    __shared__ float sA[TILE][PAD];   // sweep1: Q tile; sweep2: P tile
    __shared__ float sB[TILE][PAD];   // sweep1: K tile; sweep2: V tile
    __shared__ float s_m[TILE];
    __shared__ float s_l[TILE];

    const int b    = blockIdx.y;
    const int q0   = blockIdx.x * TILE;
    const int tx   = threadIdx.x;          // 0..15 (cols)
    const int ty   = threadIdx.y;          // 0..15 (rows)
    const int tid  = ty * 16 + tx;
    const int durb = dur[b];

    const float* Qb = q + (size_t)b * LL * DD;
    const float* Kb = k + (size_t)b * LL * DD;
    const float* Vb = v + (size_t)b * LL * DD;
    float*       Sb = score + (size_t)b * LL * LL;

    // ---- Load Q tile (rows q0..q0+63, zero-padded past L) ----
    for (int i = tid; i < TILE * (DD / 4); i += 256) {
        int r = i >> 4, c = (i & 15) << 2;
        float4 val = make_float4(0.f, 0.f, 0.f, 0.f);
        if (q0 + r < LL) val = *(const float4*)(Qb + (size_t)(q0 + r) * DD + c);
        sA[r][c] = val.x; sA[r][c + 1] = val.y; sA[r][c + 2] = val.z; sA[r][c + 3] = val.w;
    }

    float mloc[4] = {-INFINITY, -INFINITY, -INFINITY, -INFINITY};

    // ================= Sweep 1: S = mask(QK^T / 8), write raw, track row max =================
    for (int kt = 0; kt < NKT; kt++) {
        const int c0 = kt * TILE;
        __syncthreads();
        for (int i = tid; i < TILE * (DD / 4); i += 256) {
            int r = i >> 4, c = (i & 15) << 2;
            float4 val = make_float4(0.f, 0.f, 0.f, 0.f);
            if (c0 + r < LL) val = *(const float4*)(Kb + (size_t)(c0 + r) * DD + c);
            sB[r][c] = val.x; sB[r][c + 1] = val.y; sB[r][c + 2] = val.z; sB[r][c + 3] = val.w;
        }
        __syncthreads();

        float acc[4][4] = {};
        #pragma unroll 16
        for (int d = 0; d < DD; d++) {
            float a0 = sA[ty * 4 + 0][d], a1 = sA[ty * 4 + 1][d];
            float a2 = sA[ty * 4 + 2][d], a3 = sA[ty * 4 + 3][d];
            float b0 = sB[tx * 4 + 0][d], b1 = sB[tx * 4 + 1][d];
            float b2 = sB[tx * 4 + 2][d], b3 = sB[tx * 4 + 3][d];
            acc[0][0] += a0 * b0; acc[0][1] += a0 * b1; acc[0][2] += a0 * b2; acc[0][3] += a0 * b3;
            acc[1][0] += a1 * b0; acc[1][1] += a1 * b1; acc[1][2] += a1 * b2; acc[1][3] += a1 * b3;
            acc[2][0] += a2 * b0; acc[2][1] += a2 * b1; acc[2][2] += a2 * b2; acc[2][3] += a2 * b3;
            acc[3][0] += a3 * b0; acc[3][1] += a3 * b1; acc[3][2] += a3 * b2; acc[3][3] += a3 * b3;
        }

        #pragma unroll
        for (int i = 0; i < 4; i++) {
            const int r = q0 + ty * 4 + i;
            float sv[4];
            #pragma unroll
            for (int j = 0; j < 4; j++) {
                const int c = c0 + tx * 4 + j;
                float s;
                if (c >= LL) {
                    s = -INFINITY;                 // out-of-range col: never stored, excluded from max
                } else {
                    s = acc[i][j] * 0.125f;        // 1/sqrt(64)
                    if (r >= durb || c >= durb) s = -1e-12f;  // faithful ragged mask
                }
                mloc[i] = fmaxf(mloc[i], s);
                sv[j] = s;
            }
            // 900 % 4 == 0 -> each float4 col group is fully in-range or fully out
            if (r < LL && (c0 + tx * 4) < LL)
                *(float4*)(Sb + (size_t)r * LL + (c0 + tx * 4)) =
                    make_float4(sv[0], sv[1], sv[2], sv[3]);
        }
    }

    // ---- Row-max reduce across the 16 tx lanes (xor<=15 stays in 16-aligned groups) ----
    #pragma unroll
    for (int i = 0; i < 4; i++) {
        float m = mloc[i];
        #pragma unroll
        for (int off = 8; off >= 1; off >>= 1)
            m = fmaxf(m, __shfl_xor_sync(0xffffffffu, m, off));
        if (tx == 0) {
            s_m[ty * 4 + i] = m;
            const int r = q0 + ty * 4 + i;
            if (r < LL) g_m[b * LL + r] = m;
        }
    }
    __syncthreads();

    // ================= Sweep 2: p = exp(s - m); l = sum p; out_acc = P @ V =================
    const int   prow  = tid >> 2;              // row within tile (0..63)
    const int   pc0   = (tid & 3) * 16;        // 16-col segment of that row
    const float m_p   = s_m[prow];
    const int   rglob = q0 + prow;

    float oacc[4][4] = {};
    float lacc = 0.f;

    for (int kt = 0; kt < NKT; kt++) {
        const int c0 = kt * TILE;
        __syncthreads();
        // V tile
        for (int i = tid; i < TILE * (DD / 4); i += 256) {
            int r = i >> 4, c = (i & 15) << 2;
            float4 val = make_float4(0.f, 0.f, 0.f, 0.f);
            if (c0 + r < LL) val = *(const float4*)(Vb + (size_t)(c0 + r) * DD + c);
            sB[r][c] = val.x; sB[r][c + 1] = val.y; sB[r][c + 2] = val.z; sB[r][c + 3] = val.w;
        }
        // Raw scores -> exp -> P tile in sA, plus partial row-sum
        #pragma unroll
        for (int u = 0; u < 4; u++) {
            const int c = c0 + pc0 + u * 4;
            float p0 = 0.f, p1 = 0.f, p2 = 0.f, p3 = 0.f;
            if (rglob < LL && c < LL) {
                float4 s4 = *(const float4*)(Sb + (size_t)rglob * LL + c);
                p0 = __expf(s4.x - m_p); p1 = __expf(s4.y - m_p);
                p2 = __expf(s4.z - m_p); p3 = __expf(s4.w - m_p);
            }
            sA[prow][pc0 + u * 4 + 0] = p0; sA[prow][pc0 + u * 4 + 1] = p1;
            sA[prow][pc0 + u * 4 + 2] = p2; sA[prow][pc0 + u * 4 + 3] = p3;
            lacc += p0 + p1 + p2 + p3;
        }
        __syncthreads();

        #pragma unroll 16
        for (int kk = 0; kk < TILE; kk++) {
            float a0 = sA[ty * 4 + 0][kk], a1 = sA[ty * 4 + 1][kk];
            float a2 = sA[ty * 4 + 2][kk], a3 = sA[ty * 4 + 3][kk];
            float b0 = sB[kk][tx * 4 + 0], b1 = sB[kk][tx * 4 + 1];
            float b2 = sB[kk][tx * 4 + 2], b3 = sB[kk][tx * 4 + 3];
            oacc[0][0] += a0 * b0; oacc[0][1] += a0 * b1; oacc[0][2] += a0 * b2; oacc[0][3] += a0 * b3;
            oacc[1][0] += a1 * b0; oacc[1][1] += a1 * b1; oacc[1][2] += a1 * b2; oacc[1][3] += a1 * b3;
            oacc[2][0] += a2 * b0; oacc[2][1] += a2 * b1; oacc[2][2] += a2 * b2; oacc[2][3] += a2 * b3;
            oacc[3][0] += a3 * b0; oacc[3][1] += a3 * b1; oacc[3][2] += a3 * b2; oacc[3][3] += a3 * b3;
        }
    }

    // Finalize row sums (reduce over the 4 lanes of each row group)
    lacc += __shfl_xor_sync(0xffffffffu, lacc, 1);
    lacc += __shfl_xor_sync(0xffffffffu, lacc, 2);
    if ((tid & 3) == 0) {
        s_l[prow] = lacc;
        if (rglob < LL) g_invl[b * LL + rglob] = 1.f / lacc;
    }
    __syncthreads();

    #pragma unroll
    for (int i = 0; i < 4; i++) {
        const int r = q0 + ty * 4 + i;
        if (r < LL) {
            const float invl = 1.f / s_l[ty * 4 + i];
            float4 o = make_float4(oacc[i][0] * invl, oacc[i][1] * invl,
                                   oacc[i][2] * invl, oacc[i][3] * invl);
            *(float4*)(out + ((size_t)b * LL + r) * DD + tx * 4) = o;
        }
    }
}

// score[i] = exp(raw - m_row) * invl_row, vectorized float4 (900 % 4 == 0: no row straddle)
__global__ __launch_bounds__(256)
void norm_score(float* __restrict__ score)
{
    const int i4 = blockIdx.x * blockDim.x + threadIdx.x;
    const int total4 = BB * LL * LL / 4;
    if (i4 >= total4) return;
    const int row = (i4 * 4) / LL;            // == b*L + r
    const float m    = g_m[row];
    const float invl = g_invl[row];
    float4 s = ((const float4*)score)[i4];
    s.x = __expf(s.x - m) * invl;
    s.y = __expf(s.y - m) * invl;
    s.z = __expf(s.z - m) * invl;
    s.w = __expf(s.w - m) * invl;
    ((float4*)score)[i4] = s;
}

extern "C" void kernel_launch(void* const* d_in, const int* in_sizes, int n_in,
                              void* d_out, int out_size)
{
    const float* q   = (const float*)d_in[0];
    const float* k   = (const float*)d_in[1];
    const float* v   = (const float*)d_in[2];
    const int*   dur = (const int*)d_in[3];

    float* out   = (float*)d_out;
    float* score = out + (size_t)BB * LL * DD;   // tuple (out, score) concatenated

    dim3 blk(16, 16);
    dim3 grd(NKT, BB);                           // 15 q-tiles x 64 batches
    attn_fused<<<grd, blk>>>(q, k, v, dur, out, score);

    const int total4 = BB * LL * LL / 4;
    norm_score<<<(total4 + 255) / 256, 256>>>(score);
}